// round 16
// baseline (speedup 1.0000x reference)
#include <cuda_runtime.h>
#include <cuda_bf16.h>
#include <cuda_fp16.h>
#include <math.h>
#include <stdint.h>

// Problem constants (fixed by the reference)
#define BS 2
#define NQ 21760
#define NV 21760
#define MROWS (BS * NQ)   // 43520
#define CHUNK 16          // consecutive queries per sampler block

__device__ __constant__ int LVL_W[4] = {128, 64, 32, 16};
__device__ __constant__ int LVL_S[4] = {0, 16384, 20480, 21504};

// ---------------- scratch (allocation-free rule: __device__ globals) --------
// g_val is HEAD-MAJOR: [b][h][pixel][32ch] fp16 (64B per pixel per head)
__device__ __align__(16) __half g_val [MROWS * 256];
__device__ float g_off [MROWS * 256];
__device__ float g_attn[MROWS * 128];

// tf32-rounded fp32 operands (bits in uint32)
__device__ __align__(16) uint32_t g_q   [MROWS * 256];
__device__ __align__(16) uint32_t g_vv  [MROWS * 256];
__device__ __align__(16) uint32_t g_samp[MROWS * 256];
__device__ __align__(16) uint32_t gWv[256 * 256];
__device__ __align__(16) uint32_t gWo[256 * 256];
__device__ __align__(16) uint32_t gWa[256 * 128];
__device__ __align__(16) uint32_t gWu[256 * 256];

// ---------------------------------------------------------------------------
__device__ __forceinline__ uint32_t tf32r(float f) {
    uint32_t r;
    asm("cvt.rna.tf32.f32 %0, %1;" : "=r"(r) : "f"(f));
    return r;
}

__device__ __forceinline__ void mma_tf32(float *d, const uint32_t *a, const uint32_t *b) {
    asm volatile(
        "mma.sync.aligned.m16n8k8.row.col.f32.tf32.tf32.f32 "
        "{%0,%1,%2,%3}, {%4,%5,%6,%7}, {%8,%9}, {%0,%1,%2,%3};\n"
        : "+f"(d[0]), "+f"(d[1]), "+f"(d[2]), "+f"(d[3])
        : "r"(a[0]), "r"(a[1]), "r"(a[2]), "r"(a[3]), "r"(b[0]), "r"(b[1]));
}

__device__ __forceinline__ void cp16(uint32_t dst, const void* src) {
    asm volatile("cp.async.cg.shared.global [%0], [%1], 16;\n" :: "r"(dst), "l"(src));
}
__device__ __forceinline__ void cp_commit() { asm volatile("cp.async.commit_group;\n"); }
__device__ __forceinline__ void cp_wait1() { asm volatile("cp.async.wait_group 1;\n"); }
__device__ __forceinline__ void cp_wait0() { asm volatile("cp.async.wait_group 0;\n"); }

// ---------------------------------------------------------------------------
// Conversion kernels: element-wise tf32 rounding
// ---------------------------------------------------------------------------
#define ACT_WORDS (MROWS * 256 / 8)   // 8 floats per thread

__global__ __launch_bounds__(256)
void convert_acts(const float* __restrict__ query, const float* __restrict__ value) {
    int idx = blockIdx.x * 256 + threadIdx.x;
    const float* src; uint32_t* dst;
    if (idx < ACT_WORDS) { src = query; dst = g_q; }
    else { idx -= ACT_WORDS; src = value; dst = g_vv; }
    float4 f0 = *(const float4*)&src[idx * 8];
    float4 f1 = *(const float4*)&src[idx * 8 + 4];
    *(uint4*)&dst[idx * 8] =
        make_uint4(tf32r(f0.x), tf32r(f0.y), tf32r(f0.z), tf32r(f0.w));
    *(uint4*)&dst[idx * 8 + 4] =
        make_uint4(tf32r(f1.x), tf32r(f1.y), tf32r(f1.z), tf32r(f1.w));
}

__global__ __launch_bounds__(256)
void convert_wts(const float* __restrict__ Wv, const float* __restrict__ Wo,
                 const float* __restrict__ Wa, const float* __restrict__ Wu) {
    int idx4 = blockIdx.x * 256 + threadIdx.x;
    const float* W; uint32_t* D;
    if (idx4 < 16384)      { W = Wv; D = gWv; }
    else if (idx4 < 32768) { idx4 -= 16384; W = Wo; D = gWo; }
    else if (idx4 < 40960) { idx4 -= 32768; W = Wa; D = gWa; }
    else                   { idx4 -= 40960; W = Wu; D = gWu; }
    float4 f = *(const float4*)&W[idx4 * 4];
    *(uint4*)&D[idx4 * 4] = make_uint4(tf32r(f.x), tf32r(f.y), tf32r(f.z), tf32r(f.w));
}

// ---------------------------------------------------------------------------
// tf32 GEMM: C[M,N] = A @ B + bias, single pass.
// Tile 128x128, BK=16 (2 x k8 MMA steps), 512 thr = 16 warps (4M x 4N),
// warp tile 32x32 -> 32 acc regs/thread -> 2 CTAs/SM (32 warps).
// 3-stage cp.async pipeline, scalar LDS for A/B (conflict-free padded).
// HALF_OUT stores head-major fp16 into g_val.
// ---------------------------------------------------------------------------
#define A_BUF_B 10240
#define B_BUF_B 8704
#define OFF_B 30720
#define DSMEM_BYTES (30720 + 3 * 8704)   // 56832

template <bool HALF_OUT>
__device__ __forceinline__ void gemm_body(
    const uint32_t* __restrict__ Ag, const uint32_t* __restrict__ Bg,
    const float* __restrict__ bias, void* __restrict__ Cp,
    int N, int bm, int bn)
{
    extern __shared__ __align__(128) char dsm[];
    const uint32_t sbase = (uint32_t)__cvta_generic_to_shared(dsm);

    const int tid  = threadIdx.x;
    const int lane = tid & 31;
    const int warp = tid >> 5;          // 0..15
    const int g = lane >> 2;
    const int t = lane & 3;
    const int warp_m = (warp & 3) * 32;
    const int warp_n = (warp >> 2) * 32;

    // cp.async staging: one A cp16 + one B cp16 per thread
    const int ar   = tid >> 2;          // A row 0..127
    const int aseg = tid & 3;           // 16B seg of the 16-word chunk
    const int br   = tid >> 5;          // B k-row 0..15
    const int bseg = tid & 31;          // 16B seg of the 128-word row

    const uint32_t aDst = ar * 80 + aseg * 16;
    const uint32_t bDst = OFF_B + br * 544 + bseg * 16;
    const uint32_t* aSrc = Ag + (size_t)(bm + ar) * 256 + aseg * 4;
    const uint32_t* bSrc = Bg + (size_t)br * N + bn + bseg * 4;

    float acc[2][4][4];
#pragma unroll
    for (int i = 0; i < 2; i++)
#pragma unroll
        for (int j = 0; j < 4; j++)
#pragma unroll
            for (int r = 0; r < 4; r++) acc[i][j][r] = 0.0f;

    auto load_chunk = [&](int stage, int buf) {
        cp16(sbase + buf * A_BUF_B + aDst, aSrc + stage * 16);
        cp16(sbase + buf * B_BUF_B + bDst, bSrc + (size_t)stage * 16 * N);
        cp_commit();
    };

    load_chunk(0, 0);
    load_chunk(1, 1);

#pragma unroll
    for (int it = 0; it < 16; it++) {
        const int buf = it % 3;
        if (it < 15) cp_wait1(); else cp_wait0();
        __syncthreads();
        if (it < 14) load_chunk(it + 2, (it + 2) % 3);

        const uint32_t* Aw = (const uint32_t*)(dsm + buf * A_BUF_B);
        const uint32_t* Bw = (const uint32_t*)(dsm + OFF_B + buf * B_BUF_B);

#pragma unroll
        for (int s = 0; s < 2; s++) {
            uint32_t bf[4][2];
#pragma unroll
            for (int nt = 0; nt < 4; nt++) {
                int cb = warp_n + nt * 8 + g;
                bf[nt][0] = Bw[(8 * s + t) * 136 + cb];
                bf[nt][1] = Bw[(8 * s + t + 4) * 136 + cb];
            }
#pragma unroll
            for (int mt = 0; mt < 2; mt++) {
                uint32_t af[4];
                int rb = (warp_m + mt * 16 + g) * 20 + 8 * s + t;
                af[0] = Aw[rb];
                af[1] = Aw[rb + 160];
                af[2] = Aw[rb + 4];
                af[3] = Aw[rb + 164];
#pragma unroll
                for (int nt = 0; nt < 4; nt++) mma_tf32(acc[mt][nt], af, bf[nt]);
            }
        }
    }

    // epilogue
    const int bb = (bm >= NQ) ? 1 : 0;   // batch (blocks never straddle)
#pragma unroll
    for (int mt = 0; mt < 2; mt++) {
        int row0 = bm + warp_m + mt * 16 + g;
#pragma unroll
        for (int nt = 0; nt < 4; nt++) {
            int col = bn + warp_n + nt * 8 + 2 * t;
            float2 bv = *(const float2*)&bias[col];
            float vx0 = acc[mt][nt][0] + bv.x, vy0 = acc[mt][nt][1] + bv.y;
            float vx1 = acc[mt][nt][2] + bv.x, vy1 = acc[mt][nt][3] + bv.y;
            if (HALF_OUT) {
                // head-major scatter: [b][h][pix][32ch]
                __half* C = (__half*)Cp;
                int hh = col >> 5, ch = col & 31;
                int pix0 = row0 - bb * NQ;
                size_t base = ((size_t)(bb * 8 + hh) * NV);
                *(__half2*)&C[(base + pix0) * 32 + ch] = __floats2half2_rn(vx0, vy0);
                *(__half2*)&C[(base + pix0 + 8) * 32 + ch] = __floats2half2_rn(vx1, vy1);
            } else {
                float* C = (float*)Cp;
                *(float2*)&C[(size_t)row0 * N + col] = make_float2(vx0, vy0);
                *(float2*)&C[(size_t)(row0 + 8) * N + col] = make_float2(vx1, vy1);
            }
        }
    }
}

// merged: y=0,1 -> val (N=256); y=2,3 -> off (N=256); y=4 -> attn (N=128)
__global__ __launch_bounds__(512, 2)
void gemm_vqa(const float* __restrict__ b_v, const float* __restrict__ b_off,
              const float* __restrict__ b_att) {
    int bm = blockIdx.x * 128;
    int y = blockIdx.y;
    if (y < 2)
        gemm_body<true>(g_vv, gWv, b_v, g_val, 256, bm, y * 128);
    else if (y < 4)
        gemm_body<false>(g_q, gWo, b_off, g_off, 256, bm, (y - 2) * 128);
    else
        gemm_body<false>(g_q, gWa, b_att, g_attn, 128, bm, 0);
}

__global__ __launch_bounds__(512, 2)
void gemm_out(const float* __restrict__ bias, float* __restrict__ out) {
    gemm_body<false>(g_samp, gWu, bias, out, 256, blockIdx.x * 128, blockIdx.y * 128);
}

// ---------------------------------------------------------------------------
// Deformable sampler v5 (unchanged): head-major value layout; x-corner pairs
// fetched with one LDG.128 spanning both corners.
// ---------------------------------------------------------------------------
__global__ __launch_bounds__(256)
void sampler(const float* __restrict__ refp) {
    __shared__ __align__(16) float smp[8][32][8];
    const unsigned FULL = 0xffffffffu;
    const int h    = threadIdx.x >> 5;
    const int lane = threadIdx.x & 31;
    const int base = blockIdx.x * CHUNK;
    const int b    = (base >= NQ) ? 1 : 0;

    const int qi = lane >> 4;
    const int p  = lane & 15;
    const int l  = p >> 2;
    const int Wl = LVL_W[l];
    const int st = LVL_S[l];

    const int cs = lane & 3;
    const int xc = (lane >> 2) & 1;
    const int yc = (lane >> 3) & 1;
    const int p2 = lane >> 4;
    const char* vbase = (const char*)g_val + ((size_t)(b * 8 + h) * NV) * 64 + cs * 16;

    for (int i = 0; i < CHUNK; i += 2) {
        const int bq  = base + i;
        const int bq2 = bq + qi;

        float logit = g_attn[(size_t)bq2 * 128 + h * 16 + p];
        float m = logit;
#pragma unroll
        for (int o = 8; o > 0; o >>= 1) m = fmaxf(m, __shfl_xor_sync(FULL, m, o));
        float e = __expf(logit - m);
        float s = e;
#pragma unroll
        for (int o = 8; o > 0; o >>= 1) s += __shfl_xor_sync(FULL, s, o);
        float aw = e / s;

        {
            float2 offv = *(const float2*)&g_off[(size_t)bq2 * 256 + h * 32 + 2 * p];
            float2 refv = *(const float2*)&refp[(size_t)bq2 * 8 + 2 * l];

            float x = refv.x * (float)Wl + offv.x - 0.5f;
            float y = refv.y * (float)Wl + offv.y - 0.5f;
            float xf = floorf(x), yf = floorf(y);
            int x0 = (int)xf, y0 = (int)yf;
            float fx = x - xf, fy = y - yf;

            float w00 = (1.0f - fx) * (1.0f - fy) * aw;
            float w10 = fx * (1.0f - fy) * aw;
            float w01 = (1.0f - fx) * fy * aw;
            float w11 = fx * fy * aw;

            bool vx0 = (x0 >= 0) && (x0 < Wl);
            bool vx1 = (x0 + 1 >= 0) && (x0 + 1 < Wl);
            bool vy0 = (y0 >= 0) && (y0 < Wl);
            bool vy1 = (y0 + 1 >= 0) && (y0 + 1 < Wl);
            w00 = (vx0 && vy0) ? w00 : 0.0f;
            w10 = (vx1 && vy0) ? w10 : 0.0f;
            w01 = (vx0 && vy1) ? w01 : 0.0f;
            w11 = (vx1 && vy1) ? w11 : 0.0f;

            int xc0 = min(max(x0, 0), Wl - 1);
            int xc1 = min(max(x0 + 1, 0), Wl - 1);
            int yc0 = min(max(y0, 0), Wl - 1);
            int yc1 = min(max(y0 + 1, 0), Wl - 1);

            int rb0 = (st + yc0 * Wl + xc0) << 6;
            int rb1 = (st + yc1 * Wl + xc0) << 6;
            int dx  = (xc1 - xc0) << 6;

            *(float4*)&smp[h][lane][0] =
                make_float4(__int_as_float(rb0), __int_as_float(dx),
                            __int_as_float(rb1), __int_as_float(dx));
            *(float4*)&smp[h][lane][4] = make_float4(w00, w10, w01, w11);
        }
        __syncwarp();

#pragma unroll
        for (int qq = 0; qq < 2; qq++) {
            float acc[8];
#pragma unroll
            for (int k = 0; k < 8; k++) acc[k] = 0.0f;

#pragma unroll
            for (int pp = 0; pp < 16; pp += 2) {
                const float* sp = smp[h][qq * 16 + pp + p2];
                float2 rbdx = *(const float2*)&sp[yc * 2];
                float w = sp[4 + yc * 2 + xc];
                int off = __float_as_int(rbdx.x) + xc * __float_as_int(rbdx.y);
                uint4 raw = __ldg((const uint4*)(vbase + off));
                float2 v0 = __half22float2(*(const __half2*)&raw.x);
                float2 v1 = __half22float2(*(const __half2*)&raw.y);
                float2 v2 = __half22float2(*(const __half2*)&raw.z);
                float2 v3 = __half22float2(*(const __half2*)&raw.w);
                acc[0] = fmaf(w, v0.x, acc[0]);
                acc[1] = fmaf(w, v0.y, acc[1]);
                acc[2] = fmaf(w, v1.x, acc[2]);
                acc[3] = fmaf(w, v1.y, acc[3]);
                acc[4] = fmaf(w, v2.x, acc[4]);
                acc[5] = fmaf(w, v2.y, acc[5]);
                acc[6] = fmaf(w, v3.x, acc[6]);
                acc[7] = fmaf(w, v3.y, acc[7]);
            }

#pragma unroll
            for (int o = 4; o <= 16; o <<= 1)
#pragma unroll
                for (int k = 0; k < 8; k++)
                    acc[k] += __shfl_xor_sync(FULL, acc[k], o);

            if (lane < 4) {
                size_t o8 = (size_t)(bq + qq) * 256 + h * 32 + lane * 8;
                *(uint4*)&g_samp[o8] =
                    make_uint4(tf32r(acc[0]), tf32r(acc[1]), tf32r(acc[2]), tf32r(acc[3]));
                *(uint4*)&g_samp[o8 + 4] =
                    make_uint4(tf32r(acc[4]), tf32r(acc[5]), tf32r(acc[6]), tf32r(acc[7]));
            }
        }
        __syncwarp();
    }
}

// ---------------------------------------------------------------------------
// kernel_launch
// Inputs: 0 query, 1 value, 2 reference_points, 3 spatial_shapes,
// 4 W_off, 5 b_off, 6 W_attn, 7 b_attn, 8 W_v, 9 b_v, 10 W_out, 11 b_out
// ---------------------------------------------------------------------------
extern "C" void kernel_launch(void* const* d_in, const int* in_sizes, int n_in,
                              void* d_out, int out_size) {
    const float* query = (const float*)d_in[0];
    const float* value = (const float*)d_in[1];
    const float* refp  = (const float*)d_in[2];
    const float* W_off = (const float*)d_in[4];
    const float* b_off = (const float*)d_in[5];
    const float* W_att = (const float*)d_in[6];
    const float* b_att = (const float*)d_in[7];
    const float* W_v   = (const float*)d_in[8];
    const float* b_v   = (const float*)d_in[9];
    const float* W_out = (const float*)d_in[10];
    const float* b_out = (const float*)d_in[11];
    float* out = (float*)d_out;

    cudaFuncSetAttribute(gemm_vqa, cudaFuncAttributeMaxDynamicSharedMemorySize, DSMEM_BYTES);
    cudaFuncSetAttribute(gemm_out, cudaFuncAttributeMaxDynamicSharedMemorySize, DSMEM_BYTES);

    dim3 blk(256);
    dim3 blkg(512);

    convert_acts<<<2 * (ACT_WORDS / 256), blk>>>(query, value);
    convert_wts<<<224, blk>>>(W_v, W_off, W_att, W_out);

    gemm_vqa<<<dim3(MROWS / 128, 5), blkg, DSMEM_BYTES>>>(b_v, b_off, b_att);
    sampler<<<MROWS / CHUNK, blk>>>(refp);
    gemm_out<<<dim3(MROWS / 128, 2), blkg, DSMEM_BYTES>>>(b_out, out);
}

// round 17
// speedup vs baseline: 1.4969x; 1.4969x over previous
#include <cuda_runtime.h>
#include <cuda_bf16.h>
#include <cuda_fp16.h>
#include <math.h>
#include <stdint.h>

// Problem constants (fixed by the reference)
#define BS 2
#define NQ 21760
#define NV 21760
#define MROWS (BS * NQ)   // 43520
#define CHUNK 16          // consecutive queries per sampler block

__device__ __constant__ int LVL_W[4] = {128, 64, 32, 16};
__device__ __constant__ int LVL_S[4] = {0, 16384, 20480, 21504};

// ---------------- scratch (allocation-free rule: __device__ globals) --------
// g_val is HEAD-MAJOR: [b][h][pixel][32ch] fp16 (64B per pixel per head)
__device__ __align__(16) __half g_val [MROWS * 256];
__device__ float g_off [MROWS * 256];
__device__ float g_attn[MROWS * 128];

// tf32-rounded fp32 operands (bits in uint32)
__device__ __align__(16) uint32_t g_q   [MROWS * 256];
__device__ __align__(16) uint32_t g_vv  [MROWS * 256];
__device__ __align__(16) uint32_t g_samp[MROWS * 256];
__device__ __align__(16) uint32_t gWv[256 * 256];
__device__ __align__(16) uint32_t gWo[256 * 256];
__device__ __align__(16) uint32_t gWa[256 * 128];
__device__ __align__(16) uint32_t gWu[256 * 256];

// ---------------------------------------------------------------------------
__device__ __forceinline__ uint32_t tf32r(float f) {
    uint32_t r;
    asm("cvt.rna.tf32.f32 %0, %1;" : "=r"(r) : "f"(f));
    return r;
}

__device__ __forceinline__ void mma_tf32(float *d, const uint32_t *a, const uint32_t *b) {
    asm volatile(
        "mma.sync.aligned.m16n8k8.row.col.f32.tf32.tf32.f32 "
        "{%0,%1,%2,%3}, {%4,%5,%6,%7}, {%8,%9}, {%0,%1,%2,%3};\n"
        : "+f"(d[0]), "+f"(d[1]), "+f"(d[2]), "+f"(d[3])
        : "r"(a[0]), "r"(a[1]), "r"(a[2]), "r"(a[3]), "r"(b[0]), "r"(b[1]));
}

__device__ __forceinline__ void cp16(uint32_t dst, const void* src) {
    asm volatile("cp.async.cg.shared.global [%0], [%1], 16;\n" :: "r"(dst), "l"(src));
}
__device__ __forceinline__ void cp_commit() { asm volatile("cp.async.commit_group;\n"); }
__device__ __forceinline__ void cp_wait1() { asm volatile("cp.async.wait_group 1;\n"); }
__device__ __forceinline__ void cp_wait0() { asm volatile("cp.async.wait_group 0;\n"); }

// ---------------------------------------------------------------------------
// Conversion kernels: element-wise tf32 rounding
// ---------------------------------------------------------------------------
#define ACT_WORDS (MROWS * 256 / 8)   // 8 floats per thread

__global__ __launch_bounds__(256)
void convert_acts(const float* __restrict__ query, const float* __restrict__ value) {
    int idx = blockIdx.x * 256 + threadIdx.x;
    const float* src; uint32_t* dst;
    if (idx < ACT_WORDS) { src = query; dst = g_q; }
    else { idx -= ACT_WORDS; src = value; dst = g_vv; }
    float4 f0 = *(const float4*)&src[idx * 8];
    float4 f1 = *(const float4*)&src[idx * 8 + 4];
    *(uint4*)&dst[idx * 8] =
        make_uint4(tf32r(f0.x), tf32r(f0.y), tf32r(f0.z), tf32r(f0.w));
    *(uint4*)&dst[idx * 8 + 4] =
        make_uint4(tf32r(f1.x), tf32r(f1.y), tf32r(f1.z), tf32r(f1.w));
}

__global__ __launch_bounds__(256)
void convert_wts(const float* __restrict__ Wv, const float* __restrict__ Wo,
                 const float* __restrict__ Wa, const float* __restrict__ Wu) {
    int idx4 = blockIdx.x * 256 + threadIdx.x;
    const float* W; uint32_t* D;
    if (idx4 < 16384)      { W = Wv; D = gWv; }
    else if (idx4 < 32768) { idx4 -= 16384; W = Wo; D = gWo; }
    else if (idx4 < 40960) { idx4 -= 32768; W = Wa; D = gWa; }
    else                   { idx4 -= 40960; W = Wu; D = gWu; }
    float4 f = *(const float4*)&W[idx4 * 4];
    *(uint4*)&D[idx4 * 4] = make_uint4(tf32r(f.x), tf32r(f.y), tf32r(f.z), tf32r(f.w));
}

// ---------------------------------------------------------------------------
// tf32 GEMM: C[M,N] = A @ B + bias, single pass.
// Tile 128x128, BK=16 (2 x k8 MMA steps), 256 thr, warp tile 64x32.
// 3-stage cp.async pipeline, scalar LDS for A/B (conflict-free padded).
// HALF_OUT stores head-major fp16 into g_val.
// ---------------------------------------------------------------------------
#define A_BUF_B 10240
#define B_BUF_B 8704
#define OFF_B 30720
#define DSMEM_BYTES (30720 + 3 * 8704)   // 56832

template <bool HALF_OUT>
__device__ __forceinline__ void gemm_body(
    const uint32_t* __restrict__ Ag, const uint32_t* __restrict__ Bg,
    const float* __restrict__ bias, void* __restrict__ Cp,
    int N, int bm, int bn)
{
    extern __shared__ __align__(128) char dsm[];
    const uint32_t sbase = (uint32_t)__cvta_generic_to_shared(dsm);

    const int tid  = threadIdx.x;
    const int lane = tid & 31;
    const int warp = tid >> 5;
    const int g = lane >> 2;
    const int t = lane & 3;
    const int warp_m = (warp >> 2) * 64;
    const int warp_n = (warp & 3) * 32;

    const int ar  = tid >> 1;
    const int asi = (tid & 1) * 2;
    const int br  = tid >> 4;
    const int bsi = (tid & 15) * 2;

    const uint32_t aDst = ar * 80 + asi * 16;
    const uint32_t bDst = OFF_B + br * 544 + bsi * 16;
    const uint32_t* aSrc = Ag + (size_t)(bm + ar) * 256 + asi * 4;
    const uint32_t* bSrc = Bg + (size_t)br * N + bn + bsi * 4;

    float acc[4][4][4];
#pragma unroll
    for (int i = 0; i < 4; i++)
#pragma unroll
        for (int j = 0; j < 4; j++)
#pragma unroll
            for (int r = 0; r < 4; r++) acc[i][j][r] = 0.0f;

    auto load_chunk = [&](int stage, int buf) {
        cp16(sbase + buf * A_BUF_B + aDst, aSrc + stage * 16);
        cp16(sbase + buf * A_BUF_B + aDst + 16, aSrc + stage * 16 + 4);
        cp16(sbase + buf * B_BUF_B + bDst, bSrc + (size_t)stage * 16 * N);
        cp16(sbase + buf * B_BUF_B + bDst + 16, bSrc + (size_t)stage * 16 * N + 4);
        cp_commit();
    };

    load_chunk(0, 0);
    load_chunk(1, 1);

#pragma unroll
    for (int it = 0; it < 16; it++) {
        const int buf = it % 3;
        if (it < 15) cp_wait1(); else cp_wait0();
        __syncthreads();
        if (it < 14) load_chunk(it + 2, (it + 2) % 3);

        const uint32_t* Aw = (const uint32_t*)(dsm + buf * A_BUF_B);
        const uint32_t* Bw = (const uint32_t*)(dsm + OFF_B + buf * B_BUF_B);

#pragma unroll
        for (int s = 0; s < 2; s++) {
            uint32_t bf[4][2];
#pragma unroll
            for (int nt = 0; nt < 4; nt++) {
                int cb = warp_n + nt * 8 + g;
                bf[nt][0] = Bw[(8 * s + t) * 136 + cb];
                bf[nt][1] = Bw[(8 * s + t + 4) * 136 + cb];
            }
#pragma unroll
            for (int mt = 0; mt < 4; mt++) {
                uint32_t af[4];
                int rb = (warp_m + mt * 16 + g) * 20 + 8 * s + t;
                af[0] = Aw[rb];
                af[1] = Aw[rb + 160];
                af[2] = Aw[rb + 4];
                af[3] = Aw[rb + 164];
#pragma unroll
                for (int nt = 0; nt < 4; nt++) mma_tf32(acc[mt][nt], af, bf[nt]);
            }
        }
    }

    // epilogue
    const int bb = (bm >= NQ) ? 1 : 0;   // batch (blocks never straddle)
#pragma unroll
    for (int mt = 0; mt < 4; mt++) {
        int row0 = bm + warp_m + mt * 16 + g;
#pragma unroll
        for (int nt = 0; nt < 4; nt++) {
            int col = bn + warp_n + nt * 8 + 2 * t;
            float2 bv = *(const float2*)&bias[col];
            float vx0 = acc[mt][nt][0] + bv.x, vy0 = acc[mt][nt][1] + bv.y;
            float vx1 = acc[mt][nt][2] + bv.x, vy1 = acc[mt][nt][3] + bv.y;
            if (HALF_OUT) {
                // head-major scatter: [b][h][pix][32ch]
                __half* C = (__half*)Cp;
                int hh = col >> 5, ch = col & 31;
                int pix0 = row0 - bb * NQ;
                size_t base = ((size_t)(bb * 8 + hh) * NV);
                *(__half2*)&C[(base + pix0) * 32 + ch] = __floats2half2_rn(vx0, vy0);
                *(__half2*)&C[(base + pix0 + 8) * 32 + ch] = __floats2half2_rn(vx1, vy1);
            } else {
                float* C = (float*)Cp;
                *(float2*)&C[(size_t)row0 * N + col] = make_float2(vx0, vy0);
                *(float2*)&C[(size_t)(row0 + 8) * N + col] = make_float2(vx1, vy1);
            }
        }
    }
}

// merged: y=0,1 -> val (N=256); y=2,3 -> off (N=256); y=4 -> attn (N=128)
__global__ __launch_bounds__(256, 2)
void gemm_vqa(const float* __restrict__ b_v, const float* __restrict__ b_off,
              const float* __restrict__ b_att) {
    int bm = blockIdx.x * 128;
    int y = blockIdx.y;
    if (y < 2)
        gemm_body<true>(g_vv, gWv, b_v, g_val, 256, bm, y * 128);
    else if (y < 4)
        gemm_body<false>(g_q, gWo, b_off, g_off, 256, bm, (y - 2) * 128);
    else
        gemm_body<false>(g_q, gWa, b_att, g_attn, 128, bm, 0);
}

__global__ __launch_bounds__(256, 2)
void gemm_out(const float* __restrict__ bias, float* __restrict__ out) {
    gemm_body<false>(g_samp, gWu, bias, out, 256, blockIdx.x * 128, blockIdx.y * 128);
}

// ---------------------------------------------------------------------------
// Deformable sampler v5: head-major value layout; x-corner pairs fetched with
// one LDG.128 spanning both corners (contiguous 64B+64B).
// ---------------------------------------------------------------------------
__global__ __launch_bounds__(256)
void sampler(const float* __restrict__ refp) {
    __shared__ __align__(16) float smp[8][32][8];
    const unsigned FULL = 0xffffffffu;
    const int h    = threadIdx.x >> 5;
    const int lane = threadIdx.x & 31;
    const int base = blockIdx.x * CHUNK;
    const int b    = (base >= NQ) ? 1 : 0;

    const int qi = lane >> 4;
    const int p  = lane & 15;
    const int l  = p >> 2;
    const int Wl = LVL_W[l];
    const int st = LVL_S[l];

    const int cs = lane & 3;
    const int xc = (lane >> 2) & 1;
    const int yc = (lane >> 3) & 1;
    const int p2 = lane >> 4;
    const char* vbase = (const char*)g_val + ((size_t)(b * 8 + h) * NV) * 64 + cs * 16;

    for (int i = 0; i < CHUNK; i += 2) {
        const int bq  = base + i;
        const int bq2 = bq + qi;

        float logit = g_attn[(size_t)bq2 * 128 + h * 16 + p];
        float m = logit;
#pragma unroll
        for (int o = 8; o > 0; o >>= 1) m = fmaxf(m, __shfl_xor_sync(FULL, m, o));
        float e = __expf(logit - m);
        float s = e;
#pragma unroll
        for (int o = 8; o > 0; o >>= 1) s += __shfl_xor_sync(FULL, s, o);
        float aw = e / s;

        {
            float2 offv = *(const float2*)&g_off[(size_t)bq2 * 256 + h * 32 + 2 * p];
            float2 refv = *(const float2*)&refp[(size_t)bq2 * 8 + 2 * l];

            float x = refv.x * (float)Wl + offv.x - 0.5f;
            float y = refv.y * (float)Wl + offv.y - 0.5f;
            float xf = floorf(x), yf = floorf(y);
            int x0 = (int)xf, y0 = (int)yf;
            float fx = x - xf, fy = y - yf;

            float w00 = (1.0f - fx) * (1.0f - fy) * aw;
            float w10 = fx * (1.0f - fy) * aw;
            float w01 = (1.0f - fx) * fy * aw;
            float w11 = fx * fy * aw;

            bool vx0 = (x0 >= 0) && (x0 < Wl);
            bool vx1 = (x0 + 1 >= 0) && (x0 + 1 < Wl);
            bool vy0 = (y0 >= 0) && (y0 < Wl);
            bool vy1 = (y0 + 1 >= 0) && (y0 + 1 < Wl);
            w00 = (vx0 && vy0) ? w00 : 0.0f;
            w10 = (vx1 && vy0) ? w10 : 0.0f;
            w01 = (vx0 && vy1) ? w01 : 0.0f;
            w11 = (vx1 && vy1) ? w11 : 0.0f;

            int xc0 = min(max(x0, 0), Wl - 1);
            int xc1 = min(max(x0 + 1, 0), Wl - 1);
            int yc0 = min(max(y0, 0), Wl - 1);
            int yc1 = min(max(y0 + 1, 0), Wl - 1);

            int rb0 = (st + yc0 * Wl + xc0) << 6;
            int rb1 = (st + yc1 * Wl + xc0) << 6;
            int dx  = (xc1 - xc0) << 6;

            *(float4*)&smp[h][lane][0] =
                make_float4(__int_as_float(rb0), __int_as_float(dx),
                            __int_as_float(rb1), __int_as_float(dx));
            *(float4*)&smp[h][lane][4] = make_float4(w00, w10, w01, w11);
        }
        __syncwarp();

#pragma unroll
        for (int qq = 0; qq < 2; qq++) {
            float acc[8];
#pragma unroll
            for (int k = 0; k < 8; k++) acc[k] = 0.0f;

#pragma unroll
            for (int pp = 0; pp < 16; pp += 2) {
                const float* sp = smp[h][qq * 16 + pp + p2];
                float2 rbdx = *(const float2*)&sp[yc * 2];
                float w = sp[4 + yc * 2 + xc];
                int off = __float_as_int(rbdx.x) + xc * __float_as_int(rbdx.y);
                uint4 raw = __ldg((const uint4*)(vbase + off));
                float2 v0 = __half22float2(*(const __half2*)&raw.x);
                float2 v1 = __half22float2(*(const __half2*)&raw.y);
                float2 v2 = __half22float2(*(const __half2*)&raw.z);
                float2 v3 = __half22float2(*(const __half2*)&raw.w);
                acc[0] = fmaf(w, v0.x, acc[0]);
                acc[1] = fmaf(w, v0.y, acc[1]);
                acc[2] = fmaf(w, v1.x, acc[2]);
                acc[3] = fmaf(w, v1.y, acc[3]);
                acc[4] = fmaf(w, v2.x, acc[4]);
                acc[5] = fmaf(w, v2.y, acc[5]);
                acc[6] = fmaf(w, v3.x, acc[6]);
                acc[7] = fmaf(w, v3.y, acc[7]);
            }

#pragma unroll
            for (int o = 4; o <= 16; o <<= 1)
#pragma unroll
                for (int k = 0; k < 8; k++)
                    acc[k] += __shfl_xor_sync(FULL, acc[k], o);

            if (lane < 4) {
                size_t o8 = (size_t)(bq + qq) * 256 + h * 32 + lane * 8;
                *(uint4*)&g_samp[o8] =
                    make_uint4(tf32r(acc[0]), tf32r(acc[1]), tf32r(acc[2]), tf32r(acc[3]));
                *(uint4*)&g_samp[o8 + 4] =
                    make_uint4(tf32r(acc[4]), tf32r(acc[5]), tf32r(acc[6]), tf32r(acc[7]));
            }
        }
        __syncwarp();
    }
}

// ---------------------------------------------------------------------------
// kernel_launch
// Inputs: 0 query, 1 value, 2 reference_points, 3 spatial_shapes,
// 4 W_off, 5 b_off, 6 W_attn, 7 b_attn, 8 W_v, 9 b_v, 10 W_out, 11 b_out
// ---------------------------------------------------------------------------
extern "C" void kernel_launch(void* const* d_in, const int* in_sizes, int n_in,
                              void* d_out, int out_size) {
    const float* query = (const float*)d_in[0];
    const float* value = (const float*)d_in[1];
    const float* refp  = (const float*)d_in[2];
    const float* W_off = (const float*)d_in[4];
    const float* b_off = (const float*)d_in[5];
    const float* W_att = (const float*)d_in[6];
    const float* b_att = (const float*)d_in[7];
    const float* W_v   = (const float*)d_in[8];
    const float* b_v   = (const float*)d_in[9];
    const float* W_out = (const float*)d_in[10];
    const float* b_out = (const float*)d_in[11];
    float* out = (float*)d_out;

    cudaFuncSetAttribute(gemm_vqa, cudaFuncAttributeMaxDynamicSharedMemorySize, DSMEM_BYTES);
    cudaFuncSetAttribute(gemm_out, cudaFuncAttributeMaxDynamicSharedMemorySize, DSMEM_BYTES);

    dim3 blk(256);

    convert_acts<<<2 * (ACT_WORDS / 256), blk>>>(query, value);
    convert_wts<<<224, blk>>>(W_v, W_off, W_att, W_out);

    gemm_vqa<<<dim3(MROWS / 128, 5), blk, DSMEM_BYTES>>>(b_v, b_off, b_att);
    sampler<<<MROWS / CHUNK, blk>>>(refp);
    gemm_out<<<dim3(MROWS / 128, 2), blk, DSMEM_BYTES>>>(b_out, out);
}